// round 15
// baseline (speedup 1.0000x reference)
#include <cuda_runtime.h>
#include <cuda_fp16.h>
#include <stdint.h>

#define F_IN 128
#define D1   64
#define H1   8
#define C2   40
#define NMAX 100352
#define MMAX 1703936   // E + N upper bound
#define LOG2E 1.44269504088896f

#define FLAG_AGG (1 << 28)
#define FLAG_PRE (1 << 29)
#define VMASK    ((1 << 24) - 1)

typedef unsigned long long u64;

// ---------------- scratch (static device allocations; zero-initialized) ----
__device__ __align__(16) __half g_h1h[NMAX * D1];   // layer1 features (fp16)
__device__ __align__(16) __half g_hmh[NMAX * D1];   // layer2 input (fp16)
__device__ __align__(16) float  g_a1s[NMAX * H1];
__device__ __align__(16) float  g_a1d[NMAX * H1];
__device__ __align__(16) __half g_h2h[NMAX * C2];   // layer2 features (fp16)
__device__ __align__(16) float  g_a2s[NMAX];
__device__ __align__(16) float  g_a2d[NMAX];
__device__ __align__(16) int    g_deg[NMAX];        // zeroed by k_scatter tail
__device__ __align__(16) int    g_row[NMAX + 1];
__device__ __align__(16) int    g_stat[256];        // lookback statuses; zeroed by k_scatter tail
__device__ __align__(16) int    g_rank[MMAX];
__device__ __align__(16) int    g_csr[MMAX];

// ---------------- helpers ----------------
__device__ __forceinline__ float elu1(float v)  { return v > 0.f ? v : (__expf(v) - 1.f); }
__device__ __forceinline__ float ex2a(float x)  { float r; asm("ex2.approx.ftz.f32 %0,%1;" : "=f"(r) : "f"(x)); return r; }
__device__ __forceinline__ u64  dup2(float x)   { u64 r; asm("mov.b64 %0,{%1,%1};" : "=l"(r) : "f"(x)); return r; }
__device__ __forceinline__ void fma2(u64& d, u64 a, u64 b) { asm("fma.rn.f32x2 %0,%1,%2,%0;" : "+l"(d) : "l"(a), "l"(b)); }
__device__ __forceinline__ float2 un2(u64 v)    { float2 f; asm("mov.b64 {%0,%1},%2;" : "=f"(f.x), "=f"(f.y) : "l"(v)); return f; }

__device__ __forceinline__ int edge_at(const void* ei, int idx, int is32)
{
    return is32 ? ((const int*)ei)[idx] : (int)((const long long*)ei)[idx];
}

// per-block edge-dtype detect: first 64 int64 values all in [0,N) => int64.
__device__ __forceinline__ int detect_is32(const void* ei, int N)
{
    __shared__ int s_is32;
    if (threadIdx.x < 32) {
        const long long* p = (const long long*)ei;
        long long v0 = p[threadIdx.x];
        long long v1 = p[threadIdx.x + 32];
        int bad = (v0 < 0 || v0 >= (long long)N) || (v1 < 0 || v1 >= (long long)N);
        unsigned m = __ballot_sync(0xffffffffu, bad);
        if (threadIdx.x == 0) s_is32 = (m != 0);
    }
    __syncthreads();
    return s_is32;
}

// ---------------- GEMM1: h1 = x @ W1  (+ scaled att-dot epilogue) ----------
__global__ __launch_bounds__(256) void k_gemm1(
    const float* __restrict__ x, const float* __restrict__ W,
    const float* __restrict__ atts, const float* __restrict__ attd, int N)
{
    __shared__ __align__(16) float Ws[32][64];
    __shared__ __align__(16) float xsT[32][132];
    __shared__ float sAs[64], sAd[64];

    int tid = threadIdx.x;
    if (tid < 64) { sAs[tid] = atts[tid] * LOG2E; sAd[tid] = attd[tid] * LOG2E; }

    int rg = tid >> 3;        // 0..31
    int cg = tid & 7;         // 0..7
    int rowBase = blockIdx.x * 128;

    u64 acc[4][4];
#pragma unroll
    for (int i = 0; i < 4; i++)
#pragma unroll
        for (int c = 0; c < 4; c++) acc[i][c] = 0ull;

    const float4* x4 = (const float4*)x;
    const float4* W4 = (const float4*)W;

    for (int kc = 0; kc < 4; kc++) {
        __syncthreads();
#pragma unroll
        for (int i = 0; i < 2; i++) {
            int f = tid + i * 256;
            int kk = f >> 4, qj = f & 15;
            ((float4*)&Ws[kk][0])[qj] = W4[(kc * 32 + kk) * 16 + qj];
        }
#pragma unroll
        for (int i = 0; i < 4; i++) {
            int f = tid + i * 256;
            int r = f >> 3, q = f & 7;
            int gr = rowBase + r;
            float4 xv = make_float4(0.f, 0.f, 0.f, 0.f);
            if (gr < N) xv = x4[(size_t)gr * 32 + kc * 8 + q];
            xsT[q * 4 + 0][r] = xv.x;
            xsT[q * 4 + 1][r] = xv.y;
            xsT[q * 4 + 2][r] = xv.z;
            xsT[q * 4 + 3][r] = xv.w;
        }
        __syncthreads();
#pragma unroll
        for (int kk = 0; kk < 32; kk++) {
            float4 xv = *(const float4*)&xsT[kk][rg * 4];
            ulonglong2 wA = *(const ulonglong2*)&Ws[kk][cg * 8];
            ulonglong2 wB = *(const ulonglong2*)&Ws[kk][cg * 8 + 4];
            u64 xd[4] = {dup2(xv.x), dup2(xv.y), dup2(xv.z), dup2(xv.w)};
#pragma unroll
            for (int i = 0; i < 4; i++) {
                fma2(acc[i][0], xd[i], wA.x);
                fma2(acc[i][1], xd[i], wA.y);
                fma2(acc[i][2], xd[i], wB.x);
                fma2(acc[i][3], xd[i], wB.y);
            }
        }
    }

#pragma unroll
    for (int i = 0; i < 4; i++) {
        int row = rowBase + rg * 4 + i;
        if (row >= N) continue;
        float o[8];
#pragma unroll
        for (int c = 0; c < 4; c++) {
            float2 v = un2(acc[i][c]);
            o[2 * c] = v.x; o[2 * c + 1] = v.y;
        }
        union { uint4 u; __half2 h[4]; } pk;
#pragma unroll
        for (int c = 0; c < 4; c++)
            pk.h[c] = __floats2half2_rn(o[2 * c], o[2 * c + 1]);
        *(uint4*)(g_h1h + (size_t)row * 64 + cg * 8) = pk.u;

        float s = 0.f, d = 0.f;
#pragma unroll
        for (int c = 0; c < 8; c++) {
            s += o[c] * sAs[cg * 8 + c];
            d += o[c] * sAd[cg * 8 + c];
        }
        g_a1s[row * 8 + cg] = s;
        g_a1d[row * 8 + cg] = d;
    }
}

// ---- k_deg: count in-degree + record per-edge rank (2 edges/thread) -------
__global__ __launch_bounds__(256) void k_deg(const void* __restrict__ ei, int E, int N)
{
    int is32 = detect_is32(ei, N);
    int t = blockIdx.x * blockDim.x + threadIdx.x;
    int i0 = 2 * t, i1 = 2 * t + 1;
    if (i1 < E) {
        int d0 = edge_at(ei, E + i0, is32);
        int d1 = edge_at(ei, E + i1, is32);
        g_rank[i0] = atomicAdd(&g_deg[d0], 1);
        g_rank[i1] = atomicAdd(&g_deg[d1], 1);
    } else if (i0 < E) {
        int d0 = edge_at(ei, E + i0, is32);
        g_rank[i0] = atomicAdd(&g_deg[d0], 1);
    }
}

// ---------------- single-kernel scan with decoupled lookback ---------------
__global__ __launch_bounds__(1024) void k_scan(int N, int M)
{
    __shared__ int sWarp[32];
    __shared__ int s_exc;
    int tid  = threadIdx.x;
    int lane = tid & 31;
    int wid  = tid >> 5;
    int bid  = blockIdx.x;
    int i = bid * 1024 + tid;

    int v = (i < N) ? (g_deg[i] + 1) : 0;   // +1 = self loop

    int x = v;
#pragma unroll
    for (int d = 1; d < 32; d <<= 1) {
        int y = __shfl_up_sync(0xffffffffu, x, d);
        if (lane >= d) x += y;
    }
    if (lane == 31) sWarp[wid] = x;
    __syncthreads();
    if (wid == 0) {
        int t = sWarp[lane];
#pragma unroll
        for (int d = 1; d < 32; d <<= 1) {
            int y = __shfl_up_sync(0xffffffffu, t, d);
            if (lane >= d) t += y;
        }
        sWarp[lane] = t;
    }
    __syncthreads();
    int incl = x + (wid ? sWarp[wid - 1] : 0);
    int blockTotal = sWarp[31];

    if (tid == 0) {
        if (bid == 0) {
            atomicExch(&g_stat[0], FLAG_PRE | blockTotal);
            s_exc = 0;
        } else {
            atomicExch(&g_stat[bid], FLAG_AGG | blockTotal);
        }
    }

    if (bid > 0 && wid == 0) {
        int run = 0, base = bid;
        for (;;) {
            int j = base - 1 - lane;
            int sv;
            if (j >= 0) {
                do { sv = atomicAdd(&g_stat[j], 0); } while (sv == 0);
            } else {
                sv = FLAG_PRE;
            }
            __syncwarp();
            unsigned pm = __ballot_sync(0xffffffffu, (sv & FLAG_PRE) != 0);
            if (pm) {
                int lp = __ffs(pm) - 1;
                if (lane <= lp) run += sv & VMASK;
                break;
            }
            run += sv & VMASK;
            base -= 32;
        }
#pragma unroll
        for (int m = 16; m > 0; m >>= 1)
            run += __shfl_xor_sync(0xffffffffu, run, m);
        if (lane == 0) {
            s_exc = run;
            atomicExch(&g_stat[bid], FLAG_PRE | (run + blockTotal));
        }
    }
    __syncthreads();

    if (i < N) g_row[i] = s_exc + incl - v;
    if (bid == gridDim.x - 1 && tid == 0) g_row[N] = M;
}

// -------- k_scatter: atomic-free CSR fill, 2 edges/thread + state reset ----
__global__ __launch_bounds__(256) void k_scatter(const void* __restrict__ ei, int E, int M, int N)
{
    int is32 = detect_is32(ei, N);
    int t = blockIdx.x * blockDim.x + threadIdx.x;
    int i0 = 2 * t, i1 = 2 * t + 1;

    if (i1 < M) {
        int s0, d0, s1, d1;
        if (i0 < E) { s0 = edge_at(ei, i0, is32); d0 = edge_at(ei, E + i0, is32); }
        else        { s0 = d0 = i0 - E; }
        if (i1 < E) { s1 = edge_at(ei, i1, is32); d1 = edge_at(ei, E + i1, is32); }
        else        { s1 = d1 = i1 - E; }
        int slot0 = (i0 < E) ? (g_row[d0] + g_rank[i0]) : (g_row[d0 + 1] - 1);
        int slot1 = (i1 < E) ? (g_row[d1] + g_rank[i1]) : (g_row[d1 + 1] - 1);
        g_csr[slot0] = s0;
        g_csr[slot1] = s1;
    } else if (i0 < M) {
        int s0, d0;
        if (i0 < E) { s0 = edge_at(ei, i0, is32); d0 = edge_at(ei, E + i0, is32); }
        else        { s0 = d0 = i0 - E; }
        int slot0 = (i0 < E) ? (g_row[d0] + g_rank[i0]) : (g_row[d0 + 1] - 1);
        g_csr[slot0] = s0;
    }
    if (t < N)   g_deg[t] = 0;
    if (t < 256) g_stat[t] = 0;
}

// ---- layer-1 gather: 16 lanes/node, 4 features/lane, simple rolled loop ---
__global__ __launch_bounds__(256) void k_gather1(const float* __restrict__ b1, int N)
{
    int t = blockIdx.x * 256 + threadIdx.x;
    int n = t >> 4, q = t & 15, h = q >> 1;   // head h, feature quad q
    if (n >= N) return;
    int beg = g_row[n], end = g_row[n + 1];
    float ad = g_a1d[n * 8 + h];

    float ssum = 0.f;
    float4 A = make_float4(0.f, 0.f, 0.f, 0.f);
    for (int e = beg; e < end; e++) {
        int s = g_csr[e];
        float v = g_a1s[s * 8 + h] + ad;
        float w = ex2a(fmaxf(v, 0.2f * v));
        ssum += w;
        union { uint2 u; __half2 p[2]; } pk;
        pk.u = *(const uint2*)(g_h1h + (size_t)s * 64 + q * 4);
        float2 f0 = __half22float2(pk.p[0]);
        float2 f1 = __half22float2(pk.p[1]);
        A.x += w * f0.x; A.y += w * f0.y; A.z += w * f1.x; A.w += w * f1.y;
    }
    float inv = 1.f / (ssum + 1e-16f);
    const float2* b2p = (const float2*)(b1 + q * 4);
    float2 bb0 = b2p[0], bb1 = b2p[1];
    union { uint2 u; __half2 p[2]; } pk;
    pk.p[0] = __floats2half2_rn(elu1(A.x * inv + bb0.x), elu1(A.y * inv + bb0.y));
    pk.p[1] = __floats2half2_rn(elu1(A.z * inv + bb1.x), elu1(A.w * inv + bb1.y));
    *(uint2*)(g_hmh + (size_t)n * 64 + q * 4) = pk.u;
}

// ---------------- GEMM2: h2 = hm(fp16) @ W2 (+ scaled att-dot epilogue) ----
__global__ __launch_bounds__(256) void k_gemm2(
    const float* __restrict__ W2, const float* __restrict__ as2,
    const float* __restrict__ ad2, int N)
{
    __shared__ __align__(16) float Ws[64][40];
    __shared__ __align__(16) float xsT[16][260];
    __shared__ float sA[40], sD[40];

    int tid = threadIdx.x;
    if (tid < 40) { sA[tid] = as2[tid] * LOG2E; sD[tid] = ad2[tid] * LOG2E; }
    for (int f = tid; f < 640; f += 256)
        ((float4*)&Ws[0][0])[f] = ((const float4*)W2)[f];

    int rg = tid >> 2;   // 0..63
    int cg = tid & 3;    // 0..3
    int rowBase = blockIdx.x * 256;

    u64 acc[4][5];
#pragma unroll
    for (int i = 0; i < 4; i++)
#pragma unroll
        for (int c = 0; c < 5; c++) acc[i][c] = 0ull;

    const uint4* hm4 = (const uint4*)g_hmh;   // 8 uint4 per row (64 halves)

    for (int kc = 0; kc < 4; kc++) {
        __syncthreads();
#pragma unroll
        for (int i = 0; i < 2; i++) {
            int f = tid + i * 256;        // 0..511
            int r = f >> 1, q = f & 1;
            int gr = rowBase + r;
            union { uint4 u; __half2 h[4]; } pk;
            pk.u = make_uint4(0u, 0u, 0u, 0u);
            if (gr < N) pk.u = hm4[(size_t)gr * 8 + kc * 2 + q];
#pragma unroll
            for (int j = 0; j < 4; j++) {
                float2 f2 = __half22float2(pk.h[j]);
                xsT[q * 8 + 2 * j][r]     = f2.x;
                xsT[q * 8 + 2 * j + 1][r] = f2.y;
            }
        }
        __syncthreads();
#pragma unroll
        for (int kk = 0; kk < 16; kk++) {
            float4 xv = *(const float4*)&xsT[kk][rg * 4];
            const u64* wp = (const u64*)&Ws[kc * 16 + kk][cg * 10];
            u64 w0 = wp[0], w1 = wp[1], w2 = wp[2], w3 = wp[3], w4 = wp[4];
            u64 xd[4] = {dup2(xv.x), dup2(xv.y), dup2(xv.z), dup2(xv.w)};
#pragma unroll
            for (int i = 0; i < 4; i++) {
                fma2(acc[i][0], xd[i], w0);
                fma2(acc[i][1], xd[i], w1);
                fma2(acc[i][2], xd[i], w2);
                fma2(acc[i][3], xd[i], w3);
                fma2(acc[i][4], xd[i], w4);
            }
        }
    }

#pragma unroll
    for (int i = 0; i < 4; i++) {
        int row = rowBase + rg * 4 + i;
        float o[10];
#pragma unroll
        for (int c = 0; c < 5; c++) {
            float2 v = un2(acc[i][c]);
            o[2 * c] = v.x; o[2 * c + 1] = v.y;
        }
        float ps = 0.f, pd = 0.f;
#pragma unroll
        for (int c = 0; c < 10; c++) {
            ps += o[c] * sA[cg * 10 + c];
            pd += o[c] * sD[cg * 10 + c];
        }
        ps += __shfl_xor_sync(0xffffffffu, ps, 1);
        ps += __shfl_xor_sync(0xffffffffu, ps, 2);
        pd += __shfl_xor_sync(0xffffffffu, pd, 1);
        pd += __shfl_xor_sync(0xffffffffu, pd, 2);
        if (row < N) {
            __half2* hp = (__half2*)(g_h2h + (size_t)row * 40 + cg * 10);
#pragma unroll
            for (int c = 0; c < 5; c++)
                hp[c] = __floats2half2_rn(o[2 * c], o[2 * c + 1]);
            if (cg == 0) { g_a2s[row] = ps; g_a2d[row] = pd; }
        }
    }
}

// ---- layer-2 gather: 16 lanes/node; lanes 0-9 carry one class-quad each ---
__global__ __launch_bounds__(256) void k_gather2(
    const float* __restrict__ b2, float* __restrict__ out, int N)
{
    int t = blockIdx.x * 256 + threadIdx.x;
    int n = t >> 4, j = t & 15;          // j < 10: class quad [4j, 4j+4)
    bool valid = (n < N);
    if (!valid) n = N - 1;               // keep lanes alive for shfl
    int beg = g_row[n], end = g_row[n + 1];
    float ad = g_a2d[n];
    bool hasc = (j < 10);
    int jo = hasc ? j * 4 : 0;           // safe offset for inactive lanes

    float ssum = 0.f;
    float4 A = make_float4(0.f, 0.f, 0.f, 0.f);
    for (int e = beg; e < end; e++) {
        int s = g_csr[e];
        float v = g_a2s[s] + ad;
        float w = ex2a(fmaxf(v, 0.2f * v));
        ssum += w;
        union { uint2 u; __half2 p[2]; } pk;
        pk.u = *(const uint2*)(g_h2h + (size_t)s * 40 + jo);
        float2 f0 = __half22float2(pk.p[0]);
        float2 f1 = __half22float2(pk.p[1]);
        A.x += w * f0.x; A.y += w * f0.y; A.z += w * f1.x; A.w += w * f1.y;
    }
    float inv = 1.f / (ssum + 1e-16f);

    float o[4];
    float mx = -1e30f;
    if (hasc) {
        o[0] = A.x * inv + b2[j * 4 + 0];
        o[1] = A.y * inv + b2[j * 4 + 1];
        o[2] = A.z * inv + b2[j * 4 + 2];
        o[3] = A.w * inv + b2[j * 4 + 3];
        mx = fmaxf(fmaxf(o[0], o[1]), fmaxf(o[2], o[3]));
    }
#pragma unroll
    for (int msk = 1; msk < 16; msk <<= 1)
        mx = fmaxf(mx, __shfl_xor_sync(0xffffffffu, mx, msk));
    float se = 0.f;
    if (hasc) {
#pragma unroll
        for (int c = 0; c < 4; c++) se += __expf(o[c] - mx);
    }
#pragma unroll
    for (int msk = 1; msk < 16; msk <<= 1)
        se += __shfl_xor_sync(0xffffffffu, se, msk);
    float lse = mx + logf(se);

    if (valid && hasc) {
        float4 r = make_float4(o[0] - lse, o[1] - lse, o[2] - lse, o[3] - lse);
        *(float4*)(out + (size_t)n * 40 + j * 4) = r;
    }
}

// ---------------- launch ----------------
extern "C" void kernel_launch(void* const* d_in, const int* in_sizes, int n_in,
                              void* d_out, int out_size)
{
    const float* x    = (const float*)d_in[0];
    const void*  ei   = d_in[1];
    const float* W1   = (const float*)d_in[2];
    const float* as1  = (const float*)d_in[3];
    const float* ad1  = (const float*)d_in[4];
    const float* b1   = (const float*)d_in[5];
    const float* W2   = (const float*)d_in[6];
    const float* as2  = (const float*)d_in[7];
    const float* ad2  = (const float*)d_in[8];
    const float* b2   = (const float*)d_in[9];
    float*       out  = (float*)d_out;

    int N = in_sizes[0] / F_IN;
    int E = in_sizes[1] / 2;
    int M = E + N;
    int NB = (N + 1023) / 1024;
    int Eh = (E + 1) / 2;
    int Mh = (M + 1) / 2;

    static cudaStream_t s_side = nullptr;
    static cudaEvent_t  ev_fork = nullptr, ev_join = nullptr;
    if (!s_side) {
        cudaStreamCreateWithFlags(&s_side, cudaStreamNonBlocking);
        cudaEventCreateWithFlags(&ev_fork, cudaEventDisableTiming);
        cudaEventCreateWithFlags(&ev_join, cudaEventDisableTiming);
    }

    // fork: gemm1 on side stream, concurrent with CSR build
    cudaEventRecord(ev_fork, 0);
    cudaStreamWaitEvent(s_side, ev_fork, 0);
    k_gemm1<<<(N + 127) / 128, 256, 0, s_side>>>(x, W1, as1, ad1, N);
    cudaEventRecord(ev_join, s_side);

    // main chain: CSR build (deg+rank -> lookback-scan -> atomic-free scatter)
    k_deg<<<(Eh + 255) / 256, 256>>>(ei, E, N);
    k_scan<<<NB, 1024>>>(N, M);
    k_scatter<<<(Mh + 255) / 256, 256>>>(ei, E, M, N);

    // join, then attention layers (16 lanes/node gathers)
    cudaStreamWaitEvent(0, ev_join, 0);
    k_gather1<<<(N * 16 + 255) / 256, 256>>>(b1, N);
    k_gemm2<<<(N + 255) / 256, 256>>>(W2, as2, ad2, N);
    k_gather2<<<(N * 16 + 255) / 256, 256>>>(b2, out, N);
}

// round 16
// speedup vs baseline: 1.0713x; 1.0713x over previous
#include <cuda_runtime.h>
#include <cuda_fp16.h>
#include <stdint.h>

#define F_IN 128
#define D1   64
#define H1   8
#define C2   40
#define NMAX 100352
#define MMAX 1703936   // E + N upper bound
#define LOG2E 1.44269504088896f

#define FLAG_AGG (1 << 28)
#define FLAG_PRE (1 << 29)
#define VMASK    ((1 << 24) - 1)

typedef unsigned long long u64;

// ---------------- scratch (static device allocations; zero-initialized) ----
__device__ __align__(16) __half g_h1h[NMAX * D1];   // layer1 features (fp16)
__device__ __align__(16) __half g_hmh[NMAX * D1];   // layer2 input (fp16)
__device__ __align__(16) float  g_a1s[NMAX * H1];
__device__ __align__(16) float  g_a1d[NMAX * H1];
__device__ __align__(16) __half g_h2h[NMAX * C2];   // layer2 features (fp16)
__device__ __align__(16) float  g_a2s[NMAX];
__device__ __align__(16) float  g_a2d[NMAX];
__device__ __align__(16) int    g_deg[NMAX];        // zeroed by k_scatter tail
__device__ __align__(16) int    g_row[NMAX + 1];
__device__ __align__(16) int    g_stat[256];        // lookback statuses; zeroed by k_scatter tail
__device__ __align__(16) int    g_rank[MMAX];
__device__ __align__(16) int    g_csr[MMAX];

// ---------------- helpers ----------------
__device__ __forceinline__ float elu1(float v)  { return v > 0.f ? v : (__expf(v) - 1.f); }
__device__ __forceinline__ float ex2a(float x)  { float r; asm("ex2.approx.ftz.f32 %0,%1;" : "=f"(r) : "f"(x)); return r; }
__device__ __forceinline__ u64  dup2(float x)   { u64 r; asm("mov.b64 %0,{%1,%1};" : "=l"(r) : "f"(x)); return r; }
__device__ __forceinline__ void fma2(u64& d, u64 a, u64 b) { asm("fma.rn.f32x2 %0,%1,%2,%0;" : "+l"(d) : "l"(a), "l"(b)); }
__device__ __forceinline__ float2 un2(u64 v)    { float2 f; asm("mov.b64 {%0,%1},%2;" : "=f"(f.x), "=f"(f.y) : "l"(v)); return f; }

__device__ __forceinline__ int edge_at(const void* ei, int idx, int is32)
{
    return is32 ? ((const int*)ei)[idx] : (int)((const long long*)ei)[idx];
}

// per-block edge-dtype detect: first 64 int64 values all in [0,N) => int64.
__device__ __forceinline__ int detect_is32(const void* ei, int N)
{
    __shared__ int s_is32;
    if (threadIdx.x < 32) {
        const long long* p = (const long long*)ei;
        long long v0 = p[threadIdx.x];
        long long v1 = p[threadIdx.x + 32];
        int bad = (v0 < 0 || v0 >= (long long)N) || (v1 < 0 || v1 >= (long long)N);
        unsigned m = __ballot_sync(0xffffffffu, bad);
        if (threadIdx.x == 0) s_is32 = (m != 0);
    }
    __syncthreads();
    return s_is32;
}

// ---------------- GEMM1: h1 = x @ W1  (+ scaled att-dot epilogue) ----------
__global__ __launch_bounds__(256) void k_gemm1(
    const float* __restrict__ x, const float* __restrict__ W,
    const float* __restrict__ atts, const float* __restrict__ attd, int N)
{
    __shared__ __align__(16) float Ws[32][64];
    __shared__ __align__(16) float xsT[32][132];
    __shared__ float sAs[64], sAd[64];

    int tid = threadIdx.x;
    if (tid < 64) { sAs[tid] = atts[tid] * LOG2E; sAd[tid] = attd[tid] * LOG2E; }

    int rg = tid >> 3;        // 0..31
    int cg = tid & 7;         // 0..7
    int rowBase = blockIdx.x * 128;

    u64 acc[4][4];
#pragma unroll
    for (int i = 0; i < 4; i++)
#pragma unroll
        for (int c = 0; c < 4; c++) acc[i][c] = 0ull;

    const float4* x4 = (const float4*)x;
    const float4* W4 = (const float4*)W;

    for (int kc = 0; kc < 4; kc++) {
        __syncthreads();
#pragma unroll
        for (int i = 0; i < 2; i++) {
            int f = tid + i * 256;
            int kk = f >> 4, qj = f & 15;
            ((float4*)&Ws[kk][0])[qj] = W4[(kc * 32 + kk) * 16 + qj];
        }
#pragma unroll
        for (int i = 0; i < 4; i++) {
            int f = tid + i * 256;
            int r = f >> 3, q = f & 7;
            int gr = rowBase + r;
            float4 xv = make_float4(0.f, 0.f, 0.f, 0.f);
            if (gr < N) xv = x4[(size_t)gr * 32 + kc * 8 + q];
            xsT[q * 4 + 0][r] = xv.x;
            xsT[q * 4 + 1][r] = xv.y;
            xsT[q * 4 + 2][r] = xv.z;
            xsT[q * 4 + 3][r] = xv.w;
        }
        __syncthreads();
#pragma unroll
        for (int kk = 0; kk < 32; kk++) {
            float4 xv = *(const float4*)&xsT[kk][rg * 4];
            ulonglong2 wA = *(const ulonglong2*)&Ws[kk][cg * 8];
            ulonglong2 wB = *(const ulonglong2*)&Ws[kk][cg * 8 + 4];
            u64 xd[4] = {dup2(xv.x), dup2(xv.y), dup2(xv.z), dup2(xv.w)};
#pragma unroll
            for (int i = 0; i < 4; i++) {
                fma2(acc[i][0], xd[i], wA.x);
                fma2(acc[i][1], xd[i], wA.y);
                fma2(acc[i][2], xd[i], wB.x);
                fma2(acc[i][3], xd[i], wB.y);
            }
        }
    }

#pragma unroll
    for (int i = 0; i < 4; i++) {
        int row = rowBase + rg * 4 + i;
        if (row >= N) continue;
        float o[8];
#pragma unroll
        for (int c = 0; c < 4; c++) {
            float2 v = un2(acc[i][c]);
            o[2 * c] = v.x; o[2 * c + 1] = v.y;
        }
        union { uint4 u; __half2 h[4]; } pk;
#pragma unroll
        for (int c = 0; c < 4; c++)
            pk.h[c] = __floats2half2_rn(o[2 * c], o[2 * c + 1]);
        *(uint4*)(g_h1h + (size_t)row * 64 + cg * 8) = pk.u;

        float s = 0.f, d = 0.f;
#pragma unroll
        for (int c = 0; c < 8; c++) {
            s += o[c] * sAs[cg * 8 + c];
            d += o[c] * sAd[cg * 8 + c];
        }
        g_a1s[row * 8 + cg] = s;
        g_a1d[row * 8 + cg] = d;
    }
}

// ---- k_deg: count in-degree + record per-edge rank (2 edges/thread) -------
__global__ __launch_bounds__(256) void k_deg(const void* __restrict__ ei, int E, int N)
{
    int is32 = detect_is32(ei, N);
    int t = blockIdx.x * blockDim.x + threadIdx.x;
    int i0 = 2 * t, i1 = 2 * t + 1;
    if (i1 < E) {
        int d0 = edge_at(ei, E + i0, is32);
        int d1 = edge_at(ei, E + i1, is32);
        g_rank[i0] = atomicAdd(&g_deg[d0], 1);
        g_rank[i1] = atomicAdd(&g_deg[d1], 1);
    } else if (i0 < E) {
        int d0 = edge_at(ei, E + i0, is32);
        g_rank[i0] = atomicAdd(&g_deg[d0], 1);
    }
}

// ---------------- single-kernel scan with decoupled lookback ---------------
__global__ __launch_bounds__(1024) void k_scan(int N, int M)
{
    __shared__ int sWarp[32];
    __shared__ int s_exc;
    int tid  = threadIdx.x;
    int lane = tid & 31;
    int wid  = tid >> 5;
    int bid  = blockIdx.x;
    int i = bid * 1024 + tid;

    int v = (i < N) ? (g_deg[i] + 1) : 0;   // +1 = self loop

    int x = v;
#pragma unroll
    for (int d = 1; d < 32; d <<= 1) {
        int y = __shfl_up_sync(0xffffffffu, x, d);
        if (lane >= d) x += y;
    }
    if (lane == 31) sWarp[wid] = x;
    __syncthreads();
    if (wid == 0) {
        int t = sWarp[lane];
#pragma unroll
        for (int d = 1; d < 32; d <<= 1) {
            int y = __shfl_up_sync(0xffffffffu, t, d);
            if (lane >= d) t += y;
        }
        sWarp[lane] = t;
    }
    __syncthreads();
    int incl = x + (wid ? sWarp[wid - 1] : 0);
    int blockTotal = sWarp[31];

    if (tid == 0) {
        if (bid == 0) {
            atomicExch(&g_stat[0], FLAG_PRE | blockTotal);
            s_exc = 0;
        } else {
            atomicExch(&g_stat[bid], FLAG_AGG | blockTotal);
        }
    }

    if (bid > 0 && wid == 0) {
        int run = 0, base = bid;
        for (;;) {
            int j = base - 1 - lane;
            int sv;
            if (j >= 0) {
                do { sv = atomicAdd(&g_stat[j], 0); } while (sv == 0);
            } else {
                sv = FLAG_PRE;
            }
            __syncwarp();
            unsigned pm = __ballot_sync(0xffffffffu, (sv & FLAG_PRE) != 0);
            if (pm) {
                int lp = __ffs(pm) - 1;
                if (lane <= lp) run += sv & VMASK;
                break;
            }
            run += sv & VMASK;
            base -= 32;
        }
#pragma unroll
        for (int m = 16; m > 0; m >>= 1)
            run += __shfl_xor_sync(0xffffffffu, run, m);
        if (lane == 0) {
            s_exc = run;
            atomicExch(&g_stat[bid], FLAG_PRE | (run + blockTotal));
        }
    }
    __syncthreads();

    if (i < N) g_row[i] = s_exc + incl - v;
    if (bid == gridDim.x - 1 && tid == 0) g_row[N] = M;
}

// -------- k_scatter (PDL secondary of k_scan): edge loads pre-sync ---------
__global__ __launch_bounds__(256) void k_scatter(const void* __restrict__ ei, int E, int M, int N)
{
    // pre-sync: everything that reads only ei (independent of k_scan)
    int is32 = detect_is32(ei, N);
    int t = blockIdx.x * blockDim.x + threadIdx.x;
    int i0 = 2 * t, i1 = 2 * t + 1;

    int s0 = 0, d0 = 0, s1 = 0, d1 = 0;
    bool has0 = (i0 < M), has1 = (i1 < M);
    if (has0) {
        if (i0 < E) { s0 = edge_at(ei, i0, is32); d0 = edge_at(ei, E + i0, is32); }
        else        { s0 = d0 = i0 - E; }
    }
    if (has1) {
        if (i1 < E) { s1 = edge_at(ei, i1, is32); d1 = edge_at(ei, E + i1, is32); }
        else        { s1 = d1 = i1 - E; }
    }

#if __CUDA_ARCH__ >= 900
    cudaGridDependencySynchronize();   // wait for k_scan's g_row / g_stat use
#endif

    if (has0) {
        int slot0 = (i0 < E) ? (g_row[d0] + g_rank[i0]) : (g_row[d0 + 1] - 1);
        g_csr[slot0] = s0;
    }
    if (has1) {
        int slot1 = (i1 < E) ? (g_row[d1] + g_rank[i1]) : (g_row[d1 + 1] - 1);
        g_csr[slot1] = s1;
    }
    // reset state (g_deg read by scan; g_stat read by scan lookback) — post-sync only
    if (t < N)   g_deg[t] = 0;
    if (t < 256) g_stat[t] = 0;
}

// ---- layer-1 gather: 8 lanes/node, fp16 features, simple rolled loop ------
__global__ __launch_bounds__(256) void k_gather1(const float* __restrict__ b1, int N)
{
    int t = blockIdx.x * 256 + threadIdx.x;
    int n = t >> 3, h = t & 7;
    if (n >= N) return;
    int beg = g_row[n], end = g_row[n + 1];
    float ad = g_a1d[n * 8 + h];

    float ssum = 0.f;
    float4 A0 = make_float4(0.f, 0.f, 0.f, 0.f), A1 = A0;
    for (int e = beg; e < end; e++) {
        int s = g_csr[e];
        float v = g_a1s[s * 8 + h] + ad;
        float w = ex2a(fmaxf(v, 0.2f * v));
        ssum += w;
        union { uint4 u; __half2 q[4]; } pk;
        pk.u = *(const uint4*)(g_h1h + (size_t)s * 64 + h * 8);
        float2 f0 = __half22float2(pk.q[0]);
        float2 f1 = __half22float2(pk.q[1]);
        float2 f2 = __half22float2(pk.q[2]);
        float2 f3 = __half22float2(pk.q[3]);
        A0.x += w * f0.x; A0.y += w * f0.y; A0.z += w * f1.x; A0.w += w * f1.y;
        A1.x += w * f2.x; A1.y += w * f2.y; A1.z += w * f3.x; A1.w += w * f3.y;
    }
#if __CUDA_ARCH__ >= 900
    cudaTriggerProgrammaticLaunchCompletion();   // only epilogue remains
#endif
    float inv = 1.f / (ssum + 1e-16f);
    const float4* b4 = (const float4*)b1;
    float4 bb0 = b4[h * 2], bb1 = b4[h * 2 + 1];
    union { uint4 u; __half2 q[4]; } pk;
    pk.q[0] = __floats2half2_rn(elu1(A0.x * inv + bb0.x), elu1(A0.y * inv + bb0.y));
    pk.q[1] = __floats2half2_rn(elu1(A0.z * inv + bb0.z), elu1(A0.w * inv + bb0.w));
    pk.q[2] = __floats2half2_rn(elu1(A1.x * inv + bb1.x), elu1(A1.y * inv + bb1.y));
    pk.q[3] = __floats2half2_rn(elu1(A1.z * inv + bb1.z), elu1(A1.w * inv + bb1.w));
    *(uint4*)(g_hmh + (size_t)n * 64 + h * 8) = pk.u;
}

// ---- GEMM2 (PDL secondary of k_gather1): weight staging pre-sync ----------
__global__ __launch_bounds__(256) void k_gemm2(
    const float* __restrict__ W2, const float* __restrict__ as2,
    const float* __restrict__ ad2, int N)
{
    __shared__ __align__(16) float Ws[64][40];
    __shared__ __align__(16) float xsT[16][260];
    __shared__ float sA[40], sD[40];

    int tid = threadIdx.x;
    // pre-sync: stage weights (harness inputs, independent of gather1)
    if (tid < 40) { sA[tid] = as2[tid] * LOG2E; sD[tid] = ad2[tid] * LOG2E; }
    for (int f = tid; f < 640; f += 256)
        ((float4*)&Ws[0][0])[f] = ((const float4*)W2)[f];

#if __CUDA_ARCH__ >= 900
    cudaGridDependencySynchronize();   // g_hmh must be complete
#endif

    int rg = tid >> 2;   // 0..63
    int cg = tid & 3;    // 0..3
    int rowBase = blockIdx.x * 256;

    u64 acc[4][5];
#pragma unroll
    for (int i = 0; i < 4; i++)
#pragma unroll
        for (int c = 0; c < 5; c++) acc[i][c] = 0ull;

    const uint4* hm4 = (const uint4*)g_hmh;   // 8 uint4 per row (64 halves)

    for (int kc = 0; kc < 4; kc++) {
        __syncthreads();
#pragma unroll
        for (int i = 0; i < 2; i++) {
            int f = tid + i * 256;        // 0..511
            int r = f >> 1, q = f & 1;
            int gr = rowBase + r;
            union { uint4 u; __half2 h[4]; } pk;
            pk.u = make_uint4(0u, 0u, 0u, 0u);
            if (gr < N) pk.u = hm4[(size_t)gr * 8 + kc * 2 + q];
#pragma unroll
            for (int j = 0; j < 4; j++) {
                float2 f2 = __half22float2(pk.h[j]);
                xsT[q * 8 + 2 * j][r]     = f2.x;
                xsT[q * 8 + 2 * j + 1][r] = f2.y;
            }
        }
        __syncthreads();
#pragma unroll
        for (int kk = 0; kk < 16; kk++) {
            float4 xv = *(const float4*)&xsT[kk][rg * 4];
            const u64* wp = (const u64*)&Ws[kc * 16 + kk][cg * 10];
            u64 w0 = wp[0], w1 = wp[1], w2 = wp[2], w3 = wp[3], w4 = wp[4];
            u64 xd[4] = {dup2(xv.x), dup2(xv.y), dup2(xv.z), dup2(xv.w)};
#pragma unroll
            for (int i = 0; i < 4; i++) {
                fma2(acc[i][0], xd[i], w0);
                fma2(acc[i][1], xd[i], w1);
                fma2(acc[i][2], xd[i], w2);
                fma2(acc[i][3], xd[i], w3);
                fma2(acc[i][4], xd[i], w4);
            }
        }
    }

#if __CUDA_ARCH__ >= 900
    cudaTriggerProgrammaticLaunchCompletion();   // only epilogue remains
#endif

#pragma unroll
    for (int i = 0; i < 4; i++) {
        int row = rowBase + rg * 4 + i;
        float o[10];
#pragma unroll
        for (int c = 0; c < 5; c++) {
            float2 v = un2(acc[i][c]);
            o[2 * c] = v.x; o[2 * c + 1] = v.y;
        }
        float ps = 0.f, pd = 0.f;
#pragma unroll
        for (int c = 0; c < 10; c++) {
            ps += o[c] * sA[cg * 10 + c];
            pd += o[c] * sD[cg * 10 + c];
        }
        ps += __shfl_xor_sync(0xffffffffu, ps, 1);
        ps += __shfl_xor_sync(0xffffffffu, ps, 2);
        pd += __shfl_xor_sync(0xffffffffu, pd, 1);
        pd += __shfl_xor_sync(0xffffffffu, pd, 2);
        if (row < N) {
            __half2* hp = (__half2*)(g_h2h + (size_t)row * 40 + cg * 10);
#pragma unroll
            for (int c = 0; c < 5; c++)
                hp[c] = __floats2half2_rn(o[2 * c], o[2 * c + 1]);
            if (cg == 0) { g_a2s[row] = ps; g_a2d[row] = pd; }
        }
    }
}

// ---- layer-2 gather (PDL secondary of gemm2): octet split, rolled loop ----
__global__ __launch_bounds__(256) void k_gather2(
    const float* __restrict__ b2, float* __restrict__ out, int N)
{
    // pre-sync: index math + row bounds (scatter output, completed long ago)
    int t = blockIdx.x * 256 + threadIdx.x;
    int n = t >> 3, j = t & 7;           // j < 5: class octet [8j, 8j+8)
    bool valid = (n < N);
    if (!valid) n = N - 1;               // keep lanes alive for shfl
    int beg = g_row[n], end = g_row[n + 1];
    bool hasc = (j < 5);
    int jo = hasc ? j * 8 : 0;

#if __CUDA_ARCH__ >= 900
    cudaGridDependencySynchronize();     // g_a2s / g_a2d / g_h2h from gemm2
#endif

    float ad = g_a2d[n];

    float ssum = 0.f;
    float acc[8] = {0.f, 0.f, 0.f, 0.f, 0.f, 0.f, 0.f, 0.f};
    for (int e = beg; e < end; e++) {
        int s = g_csr[e];
        float v = g_a2s[s] + ad;
        float w = ex2a(fmaxf(v, 0.2f * v));
        ssum += w;
        if (hasc) {
            union { uint4 u; __half2 q[4]; } pk;
            pk.u = *(const uint4*)(g_h2h + (size_t)s * 40 + jo);
#pragma unroll
            for (int c = 0; c < 4; c++) {
                float2 f = __half22float2(pk.q[c]);
                acc[2 * c]     += w * f.x;
                acc[2 * c + 1] += w * f.y;
            }
        }
    }
    float inv = 1.f / (ssum + 1e-16f);

    float o[8];
    float mx = -1e30f;
    if (hasc) {
#pragma unroll
        for (int c = 0; c < 8; c++) {
            o[c] = acc[c] * inv + b2[j * 8 + c];
            mx = fmaxf(mx, o[c]);
        }
    }
#pragma unroll
    for (int msk = 1; msk < 8; msk <<= 1)
        mx = fmaxf(mx, __shfl_xor_sync(0xffffffffu, mx, msk));
    float se = 0.f;
    if (hasc) {
#pragma unroll
        for (int c = 0; c < 8; c++) se += __expf(o[c] - mx);
    }
#pragma unroll
    for (int msk = 1; msk < 8; msk <<= 1)
        se += __shfl_xor_sync(0xffffffffu, se, msk);
    float lse = mx + logf(se);

    if (valid && hasc) {
        float* op = out + (size_t)n * 40 + j * 8;
        float4 r0 = make_float4(o[0] - lse, o[1] - lse, o[2] - lse, o[3] - lse);
        float4 r1 = make_float4(o[4] - lse, o[5] - lse, o[6] - lse, o[7] - lse);
        ((float4*)op)[0] = r0;
        ((float4*)op)[1] = r1;
    }
}

// ---------------- launch ----------------
template <typename... Args>
static void launch_pdl(void (*kern)(Args...), dim3 grid, dim3 block,
                       cudaStream_t stream, Args... args)
{
    cudaLaunchConfig_t cfg = {};
    cfg.gridDim = grid;
    cfg.blockDim = block;
    cfg.dynamicSmemBytes = 0;
    cfg.stream = stream;
    cudaLaunchAttribute attr[1];
    attr[0].id = cudaLaunchAttributeProgrammaticStreamSerialization;
    attr[0].val.programmaticStreamSerializationAllowed = 1;
    cfg.attrs = attr;
    cfg.numAttrs = 1;
    cudaLaunchKernelEx(&cfg, kern, args...);
}

extern "C" void kernel_launch(void* const* d_in, const int* in_sizes, int n_in,
                              void* d_out, int out_size)
{
    const float* x    = (const float*)d_in[0];
    const void*  ei   = d_in[1];
    const float* W1   = (const float*)d_in[2];
    const float* as1  = (const float*)d_in[3];
    const float* ad1  = (const float*)d_in[4];
    const float* b1   = (const float*)d_in[5];
    const float* W2   = (const float*)d_in[6];
    const float* as2  = (const float*)d_in[7];
    const float* ad2  = (const float*)d_in[8];
    const float* b2   = (const float*)d_in[9];
    float*       out  = (float*)d_out;

    int N = in_sizes[0] / F_IN;
    int E = in_sizes[1] / 2;
    int M = E + N;
    int NB = (N + 1023) / 1024;
    int Eh = (E + 1) / 2;
    int Mh = (M + 1) / 2;

    static cudaStream_t s_side = nullptr;
    static cudaEvent_t  ev_fork = nullptr, ev_join = nullptr;
    if (!s_side) {
        cudaStreamCreateWithFlags(&s_side, cudaStreamNonBlocking);
        cudaEventCreateWithFlags(&ev_fork, cudaEventDisableTiming);
        cudaEventCreateWithFlags(&ev_join, cudaEventDisableTiming);
    }

    // fork: gemm1 on side stream, concurrent with CSR build
    cudaEventRecord(ev_fork, 0);
    cudaStreamWaitEvent(s_side, ev_fork, 0);
    k_gemm1<<<(N + 127) / 128, 256, 0, s_side>>>(x, W1, as1, ad1, N);
    cudaEventRecord(ev_join, s_side);

    // main chain: CSR build (deg+rank -> lookback-scan -> PDL scatter)
    k_deg<<<(Eh + 255) / 256, 256>>>(ei, E, N);
    k_scan<<<NB, 1024>>>(N, M);
    launch_pdl(k_scatter, dim3((Mh + 255) / 256), dim3(256), (cudaStream_t)0,
               ei, E, M, N);

    // join, then attention layers (gather1 -> PDL gemm2 -> PDL gather2)
    cudaStreamWaitEvent(0, ev_join, 0);
    k_gather1<<<(N * 8 + 255) / 256, 256>>>(b1, N);
    launch_pdl(k_gemm2, dim3((N + 255) / 256), dim3(256), (cudaStream_t)0,
               W2, as2, ad2, N);
    launch_pdl(k_gather2, dim3((N * 8 + 255) / 256), dim3(256), (cudaStream_t)0,
               b2, out, N);
}

// round 17
// speedup vs baseline: 1.0920x; 1.0194x over previous
#include <cuda_runtime.h>
#include <cuda_fp16.h>
#include <stdint.h>

#define F_IN 128
#define D1   64
#define H1   8
#define C2   40
#define NMAX 100352
#define MMAX 1703936   // E + N upper bound
#define LOG2E 1.44269504088896f

#define FLAG_AGG (1 << 28)
#define FLAG_PRE (1 << 29)
#define VMASK    ((1 << 24) - 1)

typedef unsigned long long u64;

// ---------------- scratch (static device allocations; zero-initialized) ----
__device__ __align__(16) __half g_h1h[NMAX * D1];   // layer1 features (fp16)
__device__ __align__(16) __half g_hmh[NMAX * D1];   // layer2 input (fp16)
__device__ __align__(16) float  g_a1s[NMAX * H1];
__device__ __align__(16) float  g_a1d[NMAX * H1];
__device__ __align__(16) __half g_h2h[NMAX * C2];   // layer2 features (fp16)
__device__ __align__(16) float  g_a2s[NMAX];
__device__ __align__(16) float  g_a2d[NMAX];
__device__ __align__(16) int    g_deg[NMAX];        // zeroed by k_scatter tail
__device__ __align__(16) int    g_row[NMAX + 1];
__device__ __align__(16) int    g_stat[256];        // lookback statuses; zeroed by k_scatter tail
__device__ __align__(16) int    g_rank[MMAX];
__device__ __align__(16) int    g_csr[MMAX];

// ---------------- helpers ----------------
__device__ __forceinline__ float elu1(float v)  { return v > 0.f ? v : (__expf(v) - 1.f); }
__device__ __forceinline__ float ex2a(float x)  { float r; asm("ex2.approx.ftz.f32 %0,%1;" : "=f"(r) : "f"(x)); return r; }
__device__ __forceinline__ u64  dup2(float x)   { u64 r; asm("mov.b64 %0,{%1,%1};" : "=l"(r) : "f"(x)); return r; }
__device__ __forceinline__ void fma2(u64& d, u64 a, u64 b) { asm("fma.rn.f32x2 %0,%1,%2,%0;" : "+l"(d) : "l"(a), "l"(b)); }
__device__ __forceinline__ float2 un2(u64 v)    { float2 f; asm("mov.b64 {%0,%1},%2;" : "=f"(f.x), "=f"(f.y) : "l"(v)); return f; }

__device__ __forceinline__ int edge_at(const void* ei, int idx, int is32)
{
    return is32 ? ((const int*)ei)[idx] : (int)((const long long*)ei)[idx];
}

// per-block edge-dtype detect: first 64 int64 values all in [0,N) => int64.
__device__ __forceinline__ int detect_is32(const void* ei, int N)
{
    __shared__ int s_is32;
    if (threadIdx.x < 32) {
        const long long* p = (const long long*)ei;
        long long v0 = p[threadIdx.x];
        long long v1 = p[threadIdx.x + 32];
        int bad = (v0 < 0 || v0 >= (long long)N) || (v1 < 0 || v1 >= (long long)N);
        unsigned m = __ballot_sync(0xffffffffu, bad);
        if (threadIdx.x == 0) s_is32 = (m != 0);
    }
    __syncthreads();
    return s_is32;
}

// ---------------- GEMM1: h1 = x @ W1  (+ scaled att-dot epilogue) ----------
__global__ __launch_bounds__(256) void k_gemm1(
    const float* __restrict__ x, const float* __restrict__ W,
    const float* __restrict__ atts, const float* __restrict__ attd, int N)
{
    __shared__ __align__(16) float Ws[32][64];
    __shared__ __align__(16) float xsT[32][132];
    __shared__ float sAs[64], sAd[64];

    int tid = threadIdx.x;
    if (tid < 64) { sAs[tid] = atts[tid] * LOG2E; sAd[tid] = attd[tid] * LOG2E; }

    int rg = tid >> 3;        // 0..31
    int cg = tid & 7;         // 0..7
    int rowBase = blockIdx.x * 128;

    u64 acc[4][4];
#pragma unroll
    for (int i = 0; i < 4; i++)
#pragma unroll
        for (int c = 0; c < 4; c++) acc[i][c] = 0ull;

    const float4* x4 = (const float4*)x;
    const float4* W4 = (const float4*)W;

    for (int kc = 0; kc < 4; kc++) {
        __syncthreads();
#pragma unroll
        for (int i = 0; i < 2; i++) {
            int f = tid + i * 256;
            int kk = f >> 4, qj = f & 15;
            ((float4*)&Ws[kk][0])[qj] = W4[(kc * 32 + kk) * 16 + qj];
        }
#pragma unroll
        for (int i = 0; i < 4; i++) {
            int f = tid + i * 256;
            int r = f >> 3, q = f & 7;
            int gr = rowBase + r;
            float4 xv = make_float4(0.f, 0.f, 0.f, 0.f);
            if (gr < N) xv = x4[(size_t)gr * 32 + kc * 8 + q];
            xsT[q * 4 + 0][r] = xv.x;
            xsT[q * 4 + 1][r] = xv.y;
            xsT[q * 4 + 2][r] = xv.z;
            xsT[q * 4 + 3][r] = xv.w;
        }
        __syncthreads();
#pragma unroll
        for (int kk = 0; kk < 32; kk++) {
            float4 xv = *(const float4*)&xsT[kk][rg * 4];
            ulonglong2 wA = *(const ulonglong2*)&Ws[kk][cg * 8];
            ulonglong2 wB = *(const ulonglong2*)&Ws[kk][cg * 8 + 4];
            u64 xd[4] = {dup2(xv.x), dup2(xv.y), dup2(xv.z), dup2(xv.w)};
#pragma unroll
            for (int i = 0; i < 4; i++) {
                fma2(acc[i][0], xd[i], wA.x);
                fma2(acc[i][1], xd[i], wA.y);
                fma2(acc[i][2], xd[i], wB.x);
                fma2(acc[i][3], xd[i], wB.y);
            }
        }
    }

#pragma unroll
    for (int i = 0; i < 4; i++) {
        int row = rowBase + rg * 4 + i;
        if (row >= N) continue;
        float o[8];
#pragma unroll
        for (int c = 0; c < 4; c++) {
            float2 v = un2(acc[i][c]);
            o[2 * c] = v.x; o[2 * c + 1] = v.y;
        }
        union { uint4 u; __half2 h[4]; } pk;
#pragma unroll
        for (int c = 0; c < 4; c++)
            pk.h[c] = __floats2half2_rn(o[2 * c], o[2 * c + 1]);
        *(uint4*)(g_h1h + (size_t)row * 64 + cg * 8) = pk.u;

        float s = 0.f, d = 0.f;
#pragma unroll
        for (int c = 0; c < 8; c++) {
            s += o[c] * sAs[cg * 8 + c];
            d += o[c] * sAd[cg * 8 + c];
        }
        g_a1s[row * 8 + cg] = s;
        g_a1d[row * 8 + cg] = d;
    }
}

// ---- k_deg: count in-degree + record per-edge rank (2 edges/thread) -------
__global__ __launch_bounds__(256) void k_deg(const void* __restrict__ ei, int E, int N)
{
    int is32 = detect_is32(ei, N);
    int t = blockIdx.x * blockDim.x + threadIdx.x;
    int i0 = 2 * t, i1 = 2 * t + 1;
    if (i1 < E) {
        int d0 = edge_at(ei, E + i0, is32);
        int d1 = edge_at(ei, E + i1, is32);
        g_rank[i0] = atomicAdd(&g_deg[d0], 1);
        g_rank[i1] = atomicAdd(&g_deg[d1], 1);
    } else if (i0 < E) {
        int d0 = edge_at(ei, E + i0, is32);
        g_rank[i0] = atomicAdd(&g_deg[d0], 1);
    }
}

// ---------------- single-kernel scan with decoupled lookback ---------------
__global__ __launch_bounds__(1024) void k_scan(int N, int M)
{
    __shared__ int sWarp[32];
    __shared__ int s_exc;
    int tid  = threadIdx.x;
    int lane = tid & 31;
    int wid  = tid >> 5;
    int bid  = blockIdx.x;
    int i = bid * 1024 + tid;

    int v = (i < N) ? (g_deg[i] + 1) : 0;   // +1 = self loop

    int x = v;
#pragma unroll
    for (int d = 1; d < 32; d <<= 1) {
        int y = __shfl_up_sync(0xffffffffu, x, d);
        if (lane >= d) x += y;
    }
    if (lane == 31) sWarp[wid] = x;
    __syncthreads();
    if (wid == 0) {
        int t = sWarp[lane];
#pragma unroll
        for (int d = 1; d < 32; d <<= 1) {
            int y = __shfl_up_sync(0xffffffffu, t, d);
            if (lane >= d) t += y;
        }
        sWarp[lane] = t;
    }
    __syncthreads();
    int incl = x + (wid ? sWarp[wid - 1] : 0);
    int blockTotal = sWarp[31];

    if (tid == 0) {
        if (bid == 0) {
            atomicExch(&g_stat[0], FLAG_PRE | blockTotal);
            s_exc = 0;
        } else {
            atomicExch(&g_stat[bid], FLAG_AGG | blockTotal);
        }
    }

    if (bid > 0 && wid == 0) {
        int run = 0, base = bid;
        for (;;) {
            int j = base - 1 - lane;
            int sv;
            if (j >= 0) {
                do { sv = atomicAdd(&g_stat[j], 0); } while (sv == 0);
            } else {
                sv = FLAG_PRE;
            }
            __syncwarp();
            unsigned pm = __ballot_sync(0xffffffffu, (sv & FLAG_PRE) != 0);
            if (pm) {
                int lp = __ffs(pm) - 1;
                if (lane <= lp) run += sv & VMASK;
                break;
            }
            run += sv & VMASK;
            base -= 32;
        }
#pragma unroll
        for (int m = 16; m > 0; m >>= 1)
            run += __shfl_xor_sync(0xffffffffu, run, m);
        if (lane == 0) {
            s_exc = run;
            atomicExch(&g_stat[bid], FLAG_PRE | (run + blockTotal));
        }
    }
    __syncthreads();

    if (i < N) g_row[i] = s_exc + incl - v;
    if (bid == gridDim.x - 1 && tid == 0) g_row[N] = M;
}

// -------- k_scatter (PDL secondary of k_scan): edge loads pre-sync ---------
__global__ __launch_bounds__(256) void k_scatter(const void* __restrict__ ei, int E, int M, int N)
{
    // pre-sync: everything that reads only ei (independent of k_scan)
    int is32 = detect_is32(ei, N);
    int t = blockIdx.x * blockDim.x + threadIdx.x;
    int i0 = 2 * t, i1 = 2 * t + 1;

    int s0 = 0, d0 = 0, s1 = 0, d1 = 0;
    bool has0 = (i0 < M), has1 = (i1 < M);
    if (has0) {
        if (i0 < E) { s0 = edge_at(ei, i0, is32); d0 = edge_at(ei, E + i0, is32); }
        else        { s0 = d0 = i0 - E; }
    }
    if (has1) {
        if (i1 < E) { s1 = edge_at(ei, i1, is32); d1 = edge_at(ei, E + i1, is32); }
        else        { s1 = d1 = i1 - E; }
    }

#if __CUDA_ARCH__ >= 900
    cudaGridDependencySynchronize();   // wait for k_scan's g_row / g_stat
#endif

    if (has0) {
        int slot0 = (i0 < E) ? (g_row[d0] + g_rank[i0]) : (g_row[d0 + 1] - 1);
        g_csr[slot0] = s0;
    }
    if (has1) {
        int slot1 = (i1 < E) ? (g_row[d1] + g_rank[i1]) : (g_row[d1 + 1] - 1);
        g_csr[slot1] = s1;
    }
    // reset state for next launch (read by k_deg / k_scan) — post-sync only
    if (t < N)   g_deg[t] = 0;
    if (t < 256) g_stat[t] = 0;
}

// ---- layer-1 gather: 8 lanes/node, fp16 features, simple rolled loop ------
__global__ __launch_bounds__(256) void k_gather1(const float* __restrict__ b1, int N)
{
    int t = blockIdx.x * 256 + threadIdx.x;
    int n = t >> 3, h = t & 7;
    if (n >= N) return;
    int beg = g_row[n], end = g_row[n + 1];
    float ad = g_a1d[n * 8 + h];

    float ssum = 0.f;
    float4 A0 = make_float4(0.f, 0.f, 0.f, 0.f), A1 = A0;
    for (int e = beg; e < end; e++) {
        int s = g_csr[e];
        float v = g_a1s[s * 8 + h] + ad;
        float w = ex2a(fmaxf(v, 0.2f * v));
        ssum += w;
        union { uint4 u; __half2 q[4]; } pk;
        pk.u = *(const uint4*)(g_h1h + (size_t)s * 64 + h * 8);
        float2 f0 = __half22float2(pk.q[0]);
        float2 f1 = __half22float2(pk.q[1]);
        float2 f2 = __half22float2(pk.q[2]);
        float2 f3 = __half22float2(pk.q[3]);
        A0.x += w * f0.x; A0.y += w * f0.y; A0.z += w * f1.x; A0.w += w * f1.y;
        A1.x += w * f2.x; A1.y += w * f2.y; A1.z += w * f3.x; A1.w += w * f3.y;
    }
    float inv = 1.f / (ssum + 1e-16f);
    const float4* b4 = (const float4*)b1;
    float4 bb0 = b4[h * 2], bb1 = b4[h * 2 + 1];
    union { uint4 u; __half2 q[4]; } pk;
    pk.q[0] = __floats2half2_rn(elu1(A0.x * inv + bb0.x), elu1(A0.y * inv + bb0.y));
    pk.q[1] = __floats2half2_rn(elu1(A0.z * inv + bb0.z), elu1(A0.w * inv + bb0.w));
    pk.q[2] = __floats2half2_rn(elu1(A1.x * inv + bb1.x), elu1(A1.y * inv + bb1.y));
    pk.q[3] = __floats2half2_rn(elu1(A1.z * inv + bb1.z), elu1(A1.w * inv + bb1.w));
    *(uint4*)(g_hmh + (size_t)n * 64 + h * 8) = pk.u;
}

// ---------------- GEMM2: h2 = hm(fp16) @ W2 (+ scaled att-dot epilogue) ----
__global__ __launch_bounds__(256) void k_gemm2(
    const float* __restrict__ W2, const float* __restrict__ as2,
    const float* __restrict__ ad2, int N)
{
    __shared__ __align__(16) float Ws[64][40];
    __shared__ __align__(16) float xsT[16][260];
    __shared__ float sA[40], sD[40];

    int tid = threadIdx.x;
    if (tid < 40) { sA[tid] = as2[tid] * LOG2E; sD[tid] = ad2[tid] * LOG2E; }
    for (int f = tid; f < 640; f += 256)
        ((float4*)&Ws[0][0])[f] = ((const float4*)W2)[f];

    int rg = tid >> 2;   // 0..63
    int cg = tid & 3;    // 0..3
    int rowBase = blockIdx.x * 256;

    u64 acc[4][5];
#pragma unroll
    for (int i = 0; i < 4; i++)
#pragma unroll
        for (int c = 0; c < 5; c++) acc[i][c] = 0ull;

    const uint4* hm4 = (const uint4*)g_hmh;   // 8 uint4 per row (64 halves)

    for (int kc = 0; kc < 4; kc++) {
        __syncthreads();
#pragma unroll
        for (int i = 0; i < 2; i++) {
            int f = tid + i * 256;        // 0..511
            int r = f >> 1, q = f & 1;
            int gr = rowBase + r;
            union { uint4 u; __half2 h[4]; } pk;
            pk.u = make_uint4(0u, 0u, 0u, 0u);
            if (gr < N) pk.u = hm4[(size_t)gr * 8 + kc * 2 + q];
#pragma unroll
            for (int j = 0; j < 4; j++) {
                float2 f2 = __half22float2(pk.h[j]);
                xsT[q * 8 + 2 * j][r]     = f2.x;
                xsT[q * 8 + 2 * j + 1][r] = f2.y;
            }
        }
        __syncthreads();
#pragma unroll
        for (int kk = 0; kk < 16; kk++) {
            float4 xv = *(const float4*)&xsT[kk][rg * 4];
            const u64* wp = (const u64*)&Ws[kc * 16 + kk][cg * 10];
            u64 w0 = wp[0], w1 = wp[1], w2 = wp[2], w3 = wp[3], w4 = wp[4];
            u64 xd[4] = {dup2(xv.x), dup2(xv.y), dup2(xv.z), dup2(xv.w)};
#pragma unroll
            for (int i = 0; i < 4; i++) {
                fma2(acc[i][0], xd[i], w0);
                fma2(acc[i][1], xd[i], w1);
                fma2(acc[i][2], xd[i], w2);
                fma2(acc[i][3], xd[i], w3);
                fma2(acc[i][4], xd[i], w4);
            }
        }
    }

#pragma unroll
    for (int i = 0; i < 4; i++) {
        int row = rowBase + rg * 4 + i;
        float o[10];
#pragma unroll
        for (int c = 0; c < 5; c++) {
            float2 v = un2(acc[i][c]);
            o[2 * c] = v.x; o[2 * c + 1] = v.y;
        }
        float ps = 0.f, pd = 0.f;
#pragma unroll
        for (int c = 0; c < 10; c++) {
            ps += o[c] * sA[cg * 10 + c];
            pd += o[c] * sD[cg * 10 + c];
        }
        ps += __shfl_xor_sync(0xffffffffu, ps, 1);
        ps += __shfl_xor_sync(0xffffffffu, ps, 2);
        pd += __shfl_xor_sync(0xffffffffu, pd, 1);
        pd += __shfl_xor_sync(0xffffffffu, pd, 2);
        if (row < N) {
            __half2* hp = (__half2*)(g_h2h + (size_t)row * 40 + cg * 10);
#pragma unroll
            for (int c = 0; c < 5; c++)
                hp[c] = __floats2half2_rn(o[2 * c], o[2 * c + 1]);
            if (cg == 0) { g_a2s[row] = ps; g_a2d[row] = pd; }
        }
    }
}

// ---- layer-2 gather: 8 lanes/node; lanes 0-4 carry one class-octet each ---
__global__ __launch_bounds__(256) void k_gather2(
    const float* __restrict__ b2, float* __restrict__ out, int N)
{
    int t = blockIdx.x * 256 + threadIdx.x;
    int n = t >> 3, j = t & 7;           // j < 5: class octet [8j, 8j+8)
    bool valid = (n < N);
    if (!valid) n = N - 1;               // keep lanes alive for shfl
    int beg = g_row[n], end = g_row[n + 1];
    float ad = g_a2d[n];
    bool hasc = (j < 5);
    int jo = hasc ? j * 8 : 0;           // safe offset for inactive lanes

    float ssum = 0.f;
    float acc[8] = {0.f, 0.f, 0.f, 0.f, 0.f, 0.f, 0.f, 0.f};
    for (int e = beg; e < end; e++) {
        int s = g_csr[e];
        float v = g_a2s[s] + ad;
        float w = ex2a(fmaxf(v, 0.2f * v));
        ssum += w;
        if (hasc) {
            union { uint4 u; __half2 q[4]; } pk;
            pk.u = *(const uint4*)(g_h2h + (size_t)s * 40 + jo);
#pragma unroll
            for (int c = 0; c < 4; c++) {
                float2 f = __half22float2(pk.q[c]);
                acc[2 * c]     += w * f.x;
                acc[2 * c + 1] += w * f.y;
            }
        }
    }
    float inv = 1.f / (ssum + 1e-16f);

    float o[8];
    float mx = -1e30f;
    if (hasc) {
#pragma unroll
        for (int c = 0; c < 8; c++) {
            o[c] = acc[c] * inv + b2[j * 8 + c];
            mx = fmaxf(mx, o[c]);
        }
    }
#pragma unroll
    for (int msk = 1; msk < 8; msk <<= 1)
        mx = fmaxf(mx, __shfl_xor_sync(0xffffffffu, mx, msk));
    float se = 0.f;
    if (hasc) {
#pragma unroll
        for (int c = 0; c < 8; c++) se += __expf(o[c] - mx);
    }
#pragma unroll
    for (int msk = 1; msk < 8; msk <<= 1)
        se += __shfl_xor_sync(0xffffffffu, se, msk);
    float lse = mx + logf(se);

    if (valid && hasc) {
        float* op = out + (size_t)n * 40 + j * 8;
        float4 r0 = make_float4(o[0] - lse, o[1] - lse, o[2] - lse, o[3] - lse);
        float4 r1 = make_float4(o[4] - lse, o[5] - lse, o[6] - lse, o[7] - lse);
        ((float4*)op)[0] = r0;
        ((float4*)op)[1] = r1;
    }
}

// ---------------- launch ----------------
template <typename... Args>
static void launch_pdl(void (*kern)(Args...), dim3 grid, dim3 block,
                       cudaStream_t stream, Args... args)
{
    cudaLaunchConfig_t cfg = {};
    cfg.gridDim = grid;
    cfg.blockDim = block;
    cfg.dynamicSmemBytes = 0;
    cfg.stream = stream;
    cudaLaunchAttribute attr[1];
    attr[0].id = cudaLaunchAttributeProgrammaticStreamSerialization;
    attr[0].val.programmaticStreamSerializationAllowed = 1;
    cfg.attrs = attr;
    cfg.numAttrs = 1;
    cudaLaunchKernelEx(&cfg, kern, args...);
}

extern "C" void kernel_launch(void* const* d_in, const int* in_sizes, int n_in,
                              void* d_out, int out_size)
{
    const float* x    = (const float*)d_in[0];
    const void*  ei   = d_in[1];
    const float* W1   = (const float*)d_in[2];
    const float* as1  = (const float*)d_in[3];
    const float* ad1  = (const float*)d_in[4];
    const float* b1   = (const float*)d_in[5];
    const float* W2   = (const float*)d_in[6];
    const float* as2  = (const float*)d_in[7];
    const float* ad2  = (const float*)d_in[8];
    const float* b2   = (const float*)d_in[9];
    float*       out  = (float*)d_out;

    int N = in_sizes[0] / F_IN;
    int E = in_sizes[1] / 2;
    int M = E + N;
    int NB = (N + 1023) / 1024;
    int Eh = (E + 1) / 2;
    int Mh = (M + 1) / 2;

    static cudaStream_t s_side = nullptr;
    static cudaEvent_t  ev_fork = nullptr, ev_join = nullptr;
    if (!s_side) {
        cudaStreamCreateWithFlags(&s_side, cudaStreamNonBlocking);
        cudaEventCreateWithFlags(&ev_fork, cudaEventDisableTiming);
        cudaEventCreateWithFlags(&ev_join, cudaEventDisableTiming);
    }

    // fork: gemm1 on side stream, concurrent with CSR build
    cudaEventRecord(ev_fork, 0);
    cudaStreamWaitEvent(s_side, ev_fork, 0);
    k_gemm1<<<(N + 127) / 128, 256, 0, s_side>>>(x, W1, as1, ad1, N);
    cudaEventRecord(ev_join, s_side);

    // main chain: CSR build (deg+rank -> lookback-scan -> PDL scatter)
    k_deg<<<(Eh + 255) / 256, 256>>>(ei, E, N);
    k_scan<<<NB, 1024>>>(N, M);
    launch_pdl(k_scatter, dim3((Mh + 255) / 256), dim3(256), (cudaStream_t)0,
               ei, E, M, N);

    // join, then attention layers (plain launches — PDL hurt here)
    cudaStreamWaitEvent(0, ev_join, 0);
    k_gather1<<<(N * 8 + 255) / 256, 256>>>(b1, N);
    k_gemm2<<<(N + 255) / 256, 256>>>(W2, as2, ad2, N);
    k_gather2<<<(N * 8 + 255) / 256, 256>>>(b2, out, N);
}